// round 16
// baseline (speedup 1.0000x reference)
#include <cuda_runtime.h>
#include <cuda_fp16.h>
#include <cstdint>

#define C_DIM 256
#define HW    1024
#define NH    8
#define HD    32
#define B_DIM 8

// ---------------- scratch (device globals, no allocation) -------------------
__device__ __half g_wh[4 * C_DIM * C_DIM];      // Wq,Wk,Wv,Wp fp16 [m][k]
__device__ __half g_xh[B_DIM * HW * C_DIM];     // x^T fp16 [b][n][c]
__device__ __half g_q [B_DIM * HW * C_DIM];     // [b][n][c] (bias+scale+log2e folded)
__device__ __half g_k [B_DIM * HW * C_DIM];     // [b][n][c]
__device__ __half g_v [B_DIM * HW * C_DIM];     // [b][n][c]
__device__ __half g_at[B_DIM * HW * C_DIM];     // attention out [b][n][c]

// ---------------- helpers ---------------------------------------------------
__device__ __forceinline__ uint32_t cvta_s(const void* p) {
    uint32_t a;
    asm("{ .reg .u64 t; cvta.to.shared.u64 t, %1; cvt.u32.u64 %0, t; }"
        : "=r"(a) : "l"(p));
    return a;
}
__device__ __forceinline__ void ldsm4(uint32_t& r0, uint32_t& r1,
                                      uint32_t& r2, uint32_t& r3, uint32_t a) {
    asm volatile("ldmatrix.sync.aligned.m8n8.x4.shared.b16 {%0,%1,%2,%3}, [%4];"
                 : "=r"(r0), "=r"(r1), "=r"(r2), "=r"(r3) : "r"(a));
}
__device__ __forceinline__ void ldsm4t(uint32_t& r0, uint32_t& r1,
                                       uint32_t& r2, uint32_t& r3, uint32_t a) {
    asm volatile("ldmatrix.sync.aligned.m8n8.x4.trans.shared.b16 {%0,%1,%2,%3}, [%4];"
                 : "=r"(r0), "=r"(r1), "=r"(r2), "=r"(r3) : "r"(a));
}
__device__ __forceinline__ void mma16816(float* c, const uint32_t* a,
                                         const uint32_t* b) {
    asm volatile("mma.sync.aligned.m16n8k16.row.col.f32.f16.f16.f32 "
                 "{%0,%1,%2,%3}, {%4,%5,%6,%7}, {%8,%9}, {%0,%1,%2,%3};"
                 : "+f"(c[0]), "+f"(c[1]), "+f"(c[2]), "+f"(c[3])
                 : "r"(a[0]), "r"(a[1]), "r"(a[2]), "r"(a[3]),
                   "r"(b[0]), "r"(b[1]));
}
__device__ __forceinline__ uint32_t pack2(float a, float b) {
    __half2 h = __floats2half2_rn(a, b);
    return *reinterpret_cast<uint32_t*>(&h);
}
__device__ __forceinline__ uint32_t ex2_h2(uint32_t s) {
    uint32_t r;
    asm("ex2.approx.f16x2 %0, %1;" : "=r"(r) : "r"(s));
    return r;
}
__device__ __forceinline__ void cp16(uint32_t dst, const void* src) {
    asm volatile("cp.async.cg.shared.global [%0], [%1], 16;"
                 :: "r"(dst), "l"(src));
}
__device__ __forceinline__ void cp_commit() {
    asm volatile("cp.async.commit_group;");
}
template<int N> __device__ __forceinline__ void cp_wait() {
    asm volatile("cp.async.wait_group %0;" :: "n"(N));
}
__device__ __forceinline__ void cp_wait_n(int n) {
    switch (n) {
        case 0:  cp_wait<0>(); break;
        case 1:  cp_wait<1>(); break;
        case 2:  cp_wait<2>(); break;
        default: cp_wait<3>(); break;
    }
}

// ---------------- prep: convert weights + transpose x (one launch) ---------
__global__ __launch_bounds__(256) void prep(
    const float* __restrict__ Wq, const float* __restrict__ Wk,
    const float* __restrict__ Wv, const float* __restrict__ Wp,
    const float* __restrict__ x)
{
    const int tid = threadIdx.x;
    if (blockIdx.x < 256) {
        // float4-vectorized weight convert: 4 matrices x 16384 float4 groups
        int idx = blockIdx.x * 256 + tid;          // 0..65535 float4 groups
        int y = idx >> 14, off4 = idx & 16383;
        const float* src = (y == 0) ? Wq : (y == 1) ? Wk : (y == 2) ? Wv : Wp;
        float4 v = ((const float4*)src)[off4];
        uint2 o;
        o.x = pack2(v.x, v.y);
        o.y = pack2(v.z, v.w);
        ((uint2*)(g_wh + (size_t)y * 65536))[off4] = o;
        return;
    }
    __shared__ float t[32][33];
    int tb = blockIdx.x - 256;
    int n0 = (tb & 31) * 32, c0 = ((tb >> 5) & 7) * 32, b = tb >> 8;
    int tx = tid & 31, ty = tid >> 5;  // 32 x 8
    const float* xb = x + ((size_t)b * C_DIM + c0) * HW + n0;
    #pragma unroll
    for (int r = 0; r < 32; r += 8) t[ty + r][tx] = xb[(ty + r) * HW + tx];
    __syncthreads();
    __half* xo = g_xh + ((size_t)b * HW + n0) * C_DIM + c0;
    #pragma unroll
    for (int r = 0; r < 32; r += 8)
        xo[(ty + r) * C_DIM + tx] = __float2half(t[tx][ty + r]);
}

// ---------------- QKV GEMM: D[n][m] = X[n,:]·W[m,:] ------------------------
// 128x128 tile, K chunks of 64, 3-stage cp.async pipeline.
__global__ __launch_bounds__(256, 2) void qkv_gemm(
    const float* __restrict__ bq, const float* __restrict__ bk,
    const float* __restrict__ bv)
{
    __shared__ __align__(16) __half smA[3][128 * 64];
    __shared__ __align__(16) __half smB[3][128 * 64];
    const int tid = threadIdx.x, lane = tid & 31, w = tid >> 5;
    const int wm = w >> 1, wn = w & 1;
    const int i0 = blockIdx.x * 128;     // HW rows
    const int n0 = blockIdx.y * 128;     // out channels
    const int p  = blockIdx.z % 3, b = blockIdx.z / 3;

    const __half* Ab = g_xh + ((size_t)b * HW + i0) * C_DIM;
    const __half* Bb = g_wh + (size_t)p * C_DIM * C_DIM + (size_t)n0 * C_DIM;
    uint32_t sA[3] = { cvta_s(smA[0]), cvta_s(smA[1]), cvta_s(smA[2]) };
    uint32_t sB[3] = { cvta_s(smB[0]), cvta_s(smB[1]), cvta_s(smB[2]) };

    float acc[2][8][4] = {};

    // prefetch chunks 0 and 1 (one group each)
    #pragma unroll
    for (int pc = 0; pc < 2; pc++) {
        int k0 = pc * 64;
        #pragma unroll
        for (int s = tid; s < 1024; s += 256) {
            int row = s >> 3, c = s & 7;
            uint32_t so = row * 128 + ((c ^ (row & 7)) << 4);
            cp16(sA[pc] + so, Ab + row * C_DIM + k0 + c * 8);
            cp16(sB[pc] + so, Bb + row * C_DIM + k0 + c * 8);
        }
        cp_commit();
    }

    for (int kc = 0; kc < 4; kc++) {
        if (kc) __syncthreads();          // stage (kc+2)%3 free (compute kc-1 done)
        if (kc + 2 < 4) {
            int st = (kc + 2) % 3, k0 = (kc + 2) * 64;
            #pragma unroll
            for (int s = tid; s < 1024; s += 256) {
                int row = s >> 3, c = s & 7;
                uint32_t so = row * 128 + ((c ^ (row & 7)) << 4);
                cp16(sA[st] + so, Ab + row * C_DIM + k0 + c * 8);
                cp16(sB[st] + so, Bb + row * C_DIM + k0 + c * 8);
            }
        }
        cp_commit();
        cp_wait_n(3 - kc >= 2 ? 2 : 3 - kc);
        __syncthreads();
        const uint32_t cA = sA[kc % 3], cB = sB[kc % 3];
        #pragma unroll
        for (int ki = 0; ki < 4; ki++) {
            uint32_t a[2][4];
            #pragma unroll
            for (int mi = 0; mi < 2; mi++) {
                int r = wm * 32 + mi * 16 + (lane & 15);
                int c = ki * 2 + (lane >> 4);
                ldsm4(a[mi][0], a[mi][1], a[mi][2], a[mi][3],
                      cA + r * 128 + ((c ^ (r & 7)) << 4));
            }
            #pragma unroll
            for (int nj = 0; nj < 4; nj++) {
                int r = wn * 64 + nj * 16 + ((lane >> 4) << 3) + (lane & 7);
                int c = ki * 2 + ((lane >> 3) & 1);
                uint32_t bb[4];
                ldsm4(bb[0], bb[1], bb[2], bb[3],
                      cB + r * 128 + ((c ^ (r & 7)) << 4));
                #pragma unroll
                for (int mi = 0; mi < 2; mi++) {
                    mma16816(acc[mi][2 * nj],     a[mi], bb);
                    mma16816(acc[mi][2 * nj + 1], a[mi], bb + 2);
                }
            }
        }
    }

    const float* bias = (p == 0) ? bq : (p == 1) ? bk : bv;
    __half* dst = ((p == 0) ? g_q : (p == 1) ? g_k : g_v) + (size_t)b * HW * C_DIM;
    // Q scale = (1/sqrt(32)) * log2(e)  — softmax runs in the log2 domain
    const float scl = (p == 0) ? 0.25503485f : 1.0f;
    #pragma unroll
    for (int mi = 0; mi < 2; mi++) {
        int r0 = i0 + wm * 32 + mi * 16 + (lane >> 2);
        #pragma unroll
        for (int nf = 0; nf < 8; nf++) {
            int m = n0 + wn * 64 + nf * 8 + 2 * (lane & 3);
            float b0 = bias[m], b1 = bias[m + 1];
            *(uint32_t*)(dst + (size_t)r0 * C_DIM + m) =
                pack2((acc[mi][nf][0] + b0) * scl, (acc[mi][nf][1] + b1) * scl);
            *(uint32_t*)(dst + (size_t)(r0 + 8) * C_DIM + m) =
                pack2((acc[mi][nf][2] + b0) * scl, (acc[mi][nf][3] + b1) * scl);
        }
    }
}

// ---------------- attention: CTA per (128-row q-pair, h, b) ----------------
// 256 threads, 8 warps = (qt, wr, wc): two independent 64-row q-tiles share
// one K/V stream (traffic halved). Single-sync double buffering. Per-warp
// inner loop identical to the validated j-split version.
__global__ __launch_bounds__(256) void attn_kernel()
{
    __shared__ __align__(16) __half q_s[2][64 * 32];
    __shared__ __align__(16) __half k_s[2][128 * 32];
    __shared__ __align__(16) __half v_s[2][128 * 32];
    const int tid = threadIdx.x, lane = tid & 31, w = tid >> 5;
    const int qt = w >> 2, wr = (w >> 1) & 1, wc = w & 1;
    const int qi = blockIdx.x, h = blockIdx.y, b = blockIdx.z;

    const __half* Kb = g_k + (size_t)b * HW * C_DIM + h * HD;
    const __half* Vb = g_v + (size_t)b * HW * C_DIM + h * HD;
    uint32_t sQ = cvta_s(q_s);
    uint32_t sK[2] = { cvta_s(k_s[0]), cvta_s(k_s[1]) };
    uint32_t sV[2] = { cvta_s(v_s[0]), cvta_s(v_s[1]) };

    // Q tiles (2 x 64 rows), cooperative across CTA
    #pragma unroll
    for (int s2 = tid; s2 < 512; s2 += 256) {
        int t = s2 >> 8, row = (s2 >> 2) & 63, c = s2 & 3;
        *(uint4*)((char*)q_s + t * 4096 + row * 64 + ((c ^ ((row >> 1) & 3)) << 4)) =
            *(const uint4*)(g_q + ((size_t)b * HW + qi * 128 + t * 64 + row) * C_DIM
                            + h * HD + c * 8);
    }
    // prefetch K/V tile 0
    #pragma unroll
    for (int s2 = tid; s2 < 512; s2 += 256) {
        int row = s2 >> 2, c = s2 & 3;
        uint32_t so = row * 64 + ((c ^ ((row >> 1) & 3)) << 4);
        cp16(sK[0] + so, Kb + (size_t)row * C_DIM + c * 8);
        cp16(sV[0] + so, Vb + (size_t)row * C_DIM + c * 8);
    }
    cp_commit();
    __syncthreads();

    // Q fragments: rows qt*64 + wr*32 + rb*16 (tile-local: wr*32 + rb*16)
    uint32_t qa[2][2][4];
    #pragma unroll
    for (int rb = 0; rb < 2; rb++)
        #pragma unroll
        for (int ki = 0; ki < 2; ki++) {
            int r = wr * 32 + rb * 16 + (lane & 15);
            int c = ki * 2 + (lane >> 4);
            ldsm4(qa[rb][ki][0], qa[rb][ki][1], qa[rb][ki][2], qa[rb][ki][3],
                  sQ + qt * 4096 + r * 64 + ((c ^ ((r >> 1) & 3)) << 4));
        }

    float o[2][4][4] = {};
    float ps0[2] = {0.f, 0.f};   // row-sum partials: rows r   (pa[0], pa[2])
    float ps1[2] = {0.f, 0.f};   // rows r+8                   (pa[1], pa[3])

    for (int kt = 0; kt < 8; kt++) {
        cp_wait<0>();
        __syncthreads();   // tile kt visible; buf (kt+1)&1 free (readers done)
        if (kt + 1 < 8) {
            int nb = (kt + 1) & 1;
            #pragma unroll
            for (int s2 = tid; s2 < 512; s2 += 256) {
                int row = s2 >> 2, c = s2 & 3;
                uint32_t so = row * 64 + ((c ^ ((row >> 1) & 3)) << 4);
                cp16(sK[nb] + so, Kb + (size_t)((kt + 1) * 128 + row) * C_DIM + c * 8);
                cp16(sV[nb] + so, Vb + (size_t)((kt + 1) * 128 + row) * C_DIM + c * 8);
            }
            cp_commit();
        }
        const uint32_t cK = sK[kt & 1], cV = sV[kt & 1];

        // per 16-j chunk of this warp's j-half: S -> exp -> PV
        #pragma unroll
        for (int kf = 0; kf < 4; kf++) {
            int j0 = wc * 64 + kf * 16;
            // K fragments as B operands
            uint32_t bb[2][4];
            #pragma unroll
            for (int ki = 0; ki < 2; ki++) {
                int r = j0 + ((lane >> 4) << 3) + (lane & 7);
                int c = ki * 2 + ((lane >> 3) & 1);
                ldsm4(bb[ki][0], bb[ki][1], bb[ki][2], bb[ki][3],
                      cK + r * 64 + ((c ^ ((r >> 1) & 3)) << 4));
            }
            // S + exp -> P fragments per row-block; row sums on fma pipe
            uint32_t pa[2][4];
            #pragma unroll
            for (int rb = 0; rb < 2; rb++) {
                float sc0[4] = {0.f, 0.f, 0.f, 0.f};
                float sc1[4] = {0.f, 0.f, 0.f, 0.f};
                #pragma unroll
                for (int ki = 0; ki < 2; ki++) {
                    mma16816(sc0, qa[rb][ki], bb[ki]);
                    mma16816(sc1, qa[rb][ki], bb[ki] + 2);
                }
                pa[rb][0] = ex2_h2(pack2(sc0[0], sc0[1]));   // row r,   j 0-1
                pa[rb][1] = ex2_h2(pack2(sc0[2], sc0[3]));   // row r+8, j 0-1
                pa[rb][2] = ex2_h2(pack2(sc1[0], sc1[1]));   // row r,   j 8-9
                pa[rb][3] = ex2_h2(pack2(sc1[2], sc1[3]));   // row r+8, j 8-9
                __half2 h0 = __hadd2(*(__half2*)&pa[rb][0], *(__half2*)&pa[rb][2]);
                __half2 h1 = __hadd2(*(__half2*)&pa[rb][1], *(__half2*)&pa[rb][3]);
                float2 f0 = __half22float2(h0);
                float2 f1 = __half22float2(h1);
                ps0[rb] += f0.x + f0.y;
                ps1[rb] += f1.x + f1.y;
            }
            // V fragments + PV
            #pragma unroll
            for (int ndp = 0; ndp < 2; ndp++) {
                uint32_t vb[4];
                int r = j0 + (lane & 15);
                int ch = ndp * 2 + (lane >> 4);
                ldsm4t(vb[0], vb[1], vb[2], vb[3],
                       cV + r * 64 + ((ch ^ ((r >> 1) & 3)) << 4));
                #pragma unroll
                for (int rb = 0; rb < 2; rb++) {
                    mma16816(o[rb][ndp * 2],     pa[rb], vb);
                    mma16816(o[rb][ndp * 2 + 1], pa[rb], vb + 2);
                }
            }
        }
    }

    // reduce row-sum partials across the 4 lanes sharing each row
    #pragma unroll
    for (int rb = 0; rb < 2; rb++) {
        ps0[rb] += __shfl_xor_sync(0xffffffffu, ps0[rb], 1);
        ps0[rb] += __shfl_xor_sync(0xffffffffu, ps0[rb], 2);
        ps1[rb] += __shfl_xor_sync(0xffffffffu, ps1[rb], 1);
        ps1[rb] += __shfl_xor_sync(0xffffffffu, ps1[rb], 2);
    }

    // ---- cross-warp (j-halves) O reduction via smem, then store ----
    // tile 0 stages in k_s (16KB), tile 1 in v_s; row sums in q_s.
    __syncthreads();
    float* stageO = (qt == 0) ? (float*)k_s : (float*)v_s;   // 64 x stride 36
    float* stageS = (float*)q_s + qt * 64;                   // 64 floats
    if (wc == 1) {
        #pragma unroll
        for (int rb = 0; rb < 2; rb++) {
            int r = wr * 32 + rb * 16 + (lane >> 2);
            #pragma unroll
            for (int nd = 0; nd < 4; nd++) {
                int cc = nd * 8 + 2 * (lane & 3);
                stageO[r * 36 + cc]           = o[rb][nd][0];
                stageO[r * 36 + cc + 1]       = o[rb][nd][1];
                stageO[(r + 8) * 36 + cc]     = o[rb][nd][2];
                stageO[(r + 8) * 36 + cc + 1] = o[rb][nd][3];
            }
            if ((lane & 3) == 0) {
                stageS[r]     = ps0[rb];
                stageS[r + 8] = ps1[rb];
            }
        }
    }
    __syncthreads();
    if (wc == 0) {
        #pragma unroll
        for (int rb = 0; rb < 2; rb++) {
            int r = wr * 32 + rb * 16 + (lane >> 2);
            float rs0 = ps0[rb] + stageS[r];
            float rs1 = ps1[rb] + stageS[r + 8];
            float inv0 = 1.f / rs0, inv1 = 1.f / rs1;
            __half* dst = g_at + ((size_t)b * HW + qi * 128 + qt * 64 + r) * C_DIM
                          + h * HD;
            #pragma unroll
            for (int nd = 0; nd < 4; nd++) {
                int cc = nd * 8 + 2 * (lane & 3);
                float v0 = o[rb][nd][0] + stageO[r * 36 + cc];
                float v1 = o[rb][nd][1] + stageO[r * 36 + cc + 1];
                float v2 = o[rb][nd][2] + stageO[(r + 8) * 36 + cc];
                float v3 = o[rb][nd][3] + stageO[(r + 8) * 36 + cc + 1];
                *(uint32_t*)(dst + cc) = pack2(v0 * inv0, v1 * inv0);
                *(uint32_t*)(dst + 8 * C_DIM + cc) = pack2(v2 * inv1, v3 * inv1);
            }
        }
    }
}

// ---------------- proj + bias + residual + LayerNorm (fused) ---------------
// Persistent: grid 128 CTAs, each handles TWO 32-row tiles. Full Wp (128KB)
// + both A tiles (32KB) live in dynamic smem; ALL loads issued upfront as 4
// commit groups, so the mainloop is wait/sync/compute with no reuse hazards.
#define PLN_BOFF   0                       // B: 4 chunks x 32KB
#define PLN_AOFF   131072                  // A: 2 tiles x 16KB (4KB per chunk)
#define PLN_SMEM   (131072 + 32768)
__global__ __launch_bounds__(256) void proj_ln(
    const float* __restrict__ bp, const float* __restrict__ gamma,
    const float* __restrict__ beta, const float* __restrict__ x,
    float* __restrict__ out)
{
    extern __shared__ __align__(16) char dsm[];
    __shared__ float redS[2][32][4];
    __shared__ float redQ[2][32][4];
    const int tid = threadIdx.x, lane = tid & 31, w = tid >> 5;
    const int wm = w >> 2, wn = w & 3;
    uint32_t sm = cvta_s(dsm);

    // tile ids: T(t) = blockIdx.x + t*128 ; b = T>>5 ; i0 = (T&31)*32
    int Tb[2], Ti[2];
    #pragma unroll
    for (int t = 0; t < 2; t++) {
        int T = blockIdx.x + t * 128;
        Tb[t] = T >> 5;
        Ti[t] = (T & 31) * 32;
    }
    const __half* Bb = g_wh + (size_t)3 * C_DIM * C_DIM;

    // ---- issue ALL loads: group0 = A(t0)+A(t1)+B0 ; groups 1..3 = B1..B3 ----
    #pragma unroll
    for (int t = 0; t < 2; t++) {
        const __half* Ab = g_at + ((size_t)Tb[t] * HW + Ti[t]) * C_DIM;
        #pragma unroll
        for (int s = tid; s < 1024; s += 256) {     // 32 rows x 8 col-groups x 4 chunks
            int c4 = s >> 8, row = (s >> 3) & 31, cc = s & 7;
            cp16(sm + PLN_AOFF + t * 16384 + c4 * 4096
                     + row * 128 + ((cc ^ (row & 7)) << 4),
                 Ab + row * C_DIM + c4 * 64 + cc * 8);
        }
    }
    #pragma unroll
    for (int s = tid; s < 2048; s += 256) {         // B chunk 0
        int row = s >> 3, cc = s & 7;
        cp16(sm + row * 128 + ((cc ^ (row & 7)) << 4), Bb + row * C_DIM + cc * 8);
    }
    cp_commit();
    #pragma unroll
    for (int c4 = 1; c4 < 4; c4++) {
        #pragma unroll
        for (int s = tid; s < 2048; s += 256) {
            int row = s >> 3, cc = s & 7;
            cp16(sm + c4 * 32768 + row * 128 + ((cc ^ (row & 7)) << 4),
                 Bb + row * C_DIM + c4 * 64 + cc * 8);
        }
        cp_commit();
    }

    float acc[2][8][4] = {};

    for (int c4 = 0; c4 < 4; c4++) {
        cp_wait_n(3 - c4);
        __syncthreads();
        const uint32_t cB = sm + c4 * 32768;
        #pragma unroll
        for (int ki = 0; ki < 4; ki++) {
            uint32_t a[2][4];
            #pragma unroll
            for (int t = 0; t < 2; t++) {
                int r = wm * 16 + (lane & 15);
                int c = ki * 2 + (lane >> 4);
                ldsm4(a[t][0], a[t][1], a[t][2], a[t][3],
                      sm + PLN_AOFF + t * 16384 + c4 * 4096
                         + r * 128 + ((c ^ (r & 7)) << 4));
            }
            #pragma unroll
            for (int nj = 0; nj < 4; nj++) {
                int r = wn * 64 + nj * 16 + ((lane >> 4) << 3) + (lane & 7);
                int c = ki * 2 + ((lane >> 3) & 1);
                uint32_t bb[4];
                ldsm4(bb[0], bb[1], bb[2], bb[3],
                      cB + r * 128 + ((c ^ (r & 7)) << 4));
                #pragma unroll
                for (int t = 0; t < 2; t++) {
                    mma16816(acc[t][2 * nj],     a[t], bb);
                    mma16816(acc[t][2 * nj + 1], a[t], bb + 2);
                }
            }
        }
    }

    // ---- epilogues (both tiles): bias + residual, LN stats, store ----
    const int r0 = wm * 16 + (lane >> 2);
    #pragma unroll
    for (int t = 0; t < 2; t++) {
        float s0 = 0.f, q0 = 0.f, s1 = 0.f, q1 = 0.f;
        #pragma unroll
        for (int nf = 0; nf < 8; nf++) {
            int m = wn * 64 + nf * 8 + 2 * (lane & 3);
            const float* xp = x + ((size_t)Tb[t] * C_DIM + m) * HW + Ti[t];
            float b0 = bp[m], b1 = bp[m + 1];
            acc[t][nf][0] += b0 + xp[r0];
            acc[t][nf][1] += b1 + xp[HW + r0];
            acc[t][nf][2] += b0 + xp[r0 + 8];
            acc[t][nf][3] += b1 + xp[HW + r0 + 8];
            s0 += acc[t][nf][0] + acc[t][nf][1];
            q0 += acc[t][nf][0] * acc[t][nf][0] + acc[t][nf][1] * acc[t][nf][1];
            s1 += acc[t][nf][2] + acc[t][nf][3];
            q1 += acc[t][nf][2] * acc[t][nf][2] + acc[t][nf][3] * acc[t][nf][3];
        }
        s0 += __shfl_xor_sync(0xffffffffu, s0, 1); s0 += __shfl_xor_sync(0xffffffffu, s0, 2);
        q0 += __shfl_xor_sync(0xffffffffu, q0, 1); q0 += __shfl_xor_sync(0xffffffffu, q0, 2);
        s1 += __shfl_xor_sync(0xffffffffu, s1, 1); s1 += __shfl_xor_sync(0xffffffffu, s1, 2);
        q1 += __shfl_xor_sync(0xffffffffu, q1, 1); q1 += __shfl_xor_sync(0xffffffffu, q1, 2);
        if ((lane & 3) == 0) {
            redS[t][r0][wn] = s0; redQ[t][r0][wn] = q0;
            redS[t][r0 + 8][wn] = s1; redQ[t][r0 + 8][wn] = q1;
        }
    }
    __syncthreads();
    #pragma unroll
    for (int t = 0; t < 2; t++) {
        float mu0 = (redS[t][r0][0] + redS[t][r0][1] + redS[t][r0][2] + redS[t][r0][3])
                    * (1.f / 256.f);
        float v0  = (redQ[t][r0][0] + redQ[t][r0][1] + redQ[t][r0][2] + redQ[t][r0][3])
                    * (1.f / 256.f) - mu0 * mu0;
        float rg0 = rsqrtf(v0 + 1e-5f);
        float mu1 = (redS[t][r0 + 8][0] + redS[t][r0 + 8][1] + redS[t][r0 + 8][2]
                     + redS[t][r0 + 8][3]) * (1.f / 256.f);
        float v1  = (redQ[t][r0 + 8][0] + redQ[t][r0 + 8][1] + redQ[t][r0 + 8][2]
                     + redQ[t][r0 + 8][3]) * (1.f / 256.f) - mu1 * mu1;
        float rg1 = rsqrtf(v1 + 1e-5f);
        #pragma unroll
        for (int nf = 0; nf < 8; nf++) {
            int m = wn * 64 + nf * 8 + 2 * (lane & 3);
            float g0 = gamma[m], g1 = gamma[m + 1];
            float e0 = beta[m],  e1 = beta[m + 1];
            float* op = out + ((size_t)Tb[t] * C_DIM + m) * HW + Ti[t];
            op[r0]          = (acc[t][nf][0] - mu0) * rg0 * g0 + e0;
            op[HW + r0]     = (acc[t][nf][1] - mu0) * rg0 * g1 + e1;
            op[r0 + 8]      = (acc[t][nf][2] - mu1) * rg1 * g0 + e0;
            op[HW + r0 + 8] = (acc[t][nf][3] - mu1) * rg1 * g1 + e1;
        }
    }
}

// ---------------------------------------------------------------------------
extern "C" void kernel_launch(void* const* d_in, const int* in_sizes, int n_in,
                              void* d_out, int out_size)
{
    const float* x     = (const float*)d_in[0];
    const float* Wq    = (const float*)d_in[1];
    const float* bq    = (const float*)d_in[2];
    const float* Wk    = (const float*)d_in[3];
    const float* bk    = (const float*)d_in[4];
    const float* Wv    = (const float*)d_in[5];
    const float* bv    = (const float*)d_in[6];
    const float* Wp    = (const float*)d_in[7];
    const float* bp    = (const float*)d_in[8];
    const float* gamma = (const float*)d_in[9];
    const float* beta  = (const float*)d_in[10];
    float* out = (float*)d_out;

    cudaFuncSetAttribute(proj_ln, cudaFuncAttributeMaxDynamicSharedMemorySize,
                         PLN_SMEM);

    prep<<<2304, 256>>>(Wq, Wk, Wv, Wp, x);
    qkv_gemm<<<dim3(HW / 128, C_DIM / 128, B_DIM * 3), 256>>>(bq, bk, bv);
    attn_kernel<<<dim3(HW / 128, NH, B_DIM), 256>>>();
    proj_ln<<<128, 256, PLN_SMEM>>>(bp, gamma, beta, x, out);
}

// round 17
// speedup vs baseline: 1.1481x; 1.1481x over previous
#include <cuda_runtime.h>
#include <cuda_fp16.h>
#include <cstdint>

#define C_DIM 256
#define HW    1024
#define NH    8
#define HD    32
#define B_DIM 8

// ---------------- scratch (device globals, no allocation) -------------------
__device__ __half g_wh[4 * C_DIM * C_DIM];      // Wq,Wk,Wv,Wp fp16 [m][k]
__device__ __half g_xh[B_DIM * HW * C_DIM];     // x^T fp16 [b][n][c]
__device__ __half g_q [B_DIM * HW * C_DIM];     // [b][n][c] (bias+scale+log2e folded)
__device__ __half g_k [B_DIM * HW * C_DIM];     // [b][n][c]
__device__ __half g_v [B_DIM * HW * C_DIM];     // [b][n][c]
__device__ __half g_at[B_DIM * HW * C_DIM];     // attention out [b][n][c]

// ---------------- helpers ---------------------------------------------------
__device__ __forceinline__ uint32_t cvta_s(const void* p) {
    uint32_t a;
    asm("{ .reg .u64 t; cvta.to.shared.u64 t, %1; cvt.u32.u64 %0, t; }"
        : "=r"(a) : "l"(p));
    return a;
}
__device__ __forceinline__ void ldsm4(uint32_t& r0, uint32_t& r1,
                                      uint32_t& r2, uint32_t& r3, uint32_t a) {
    asm volatile("ldmatrix.sync.aligned.m8n8.x4.shared.b16 {%0,%1,%2,%3}, [%4];"
                 : "=r"(r0), "=r"(r1), "=r"(r2), "=r"(r3) : "r"(a));
}
__device__ __forceinline__ void ldsm4t(uint32_t& r0, uint32_t& r1,
                                       uint32_t& r2, uint32_t& r3, uint32_t a) {
    asm volatile("ldmatrix.sync.aligned.m8n8.x4.trans.shared.b16 {%0,%1,%2,%3}, [%4];"
                 : "=r"(r0), "=r"(r1), "=r"(r2), "=r"(r3) : "r"(a));
}
__device__ __forceinline__ void mma16816(float* c, const uint32_t* a,
                                         const uint32_t* b) {
    asm volatile("mma.sync.aligned.m16n8k16.row.col.f32.f16.f16.f32 "
                 "{%0,%1,%2,%3}, {%4,%5,%6,%7}, {%8,%9}, {%0,%1,%2,%3};"
                 : "+f"(c[0]), "+f"(c[1]), "+f"(c[2]), "+f"(c[3])
                 : "r"(a[0]), "r"(a[1]), "r"(a[2]), "r"(a[3]),
                   "r"(b[0]), "r"(b[1]));
}
__device__ __forceinline__ uint32_t pack2(float a, float b) {
    __half2 h = __floats2half2_rn(a, b);
    return *reinterpret_cast<uint32_t*>(&h);
}
__device__ __forceinline__ uint32_t ex2_h2(uint32_t s) {
    uint32_t r;
    asm("ex2.approx.f16x2 %0, %1;" : "=r"(r) : "r"(s));
    return r;
}
__device__ __forceinline__ void cp16(uint32_t dst, const void* src) {
    asm volatile("cp.async.cg.shared.global [%0], [%1], 16;"
                 :: "r"(dst), "l"(src));
}
__device__ __forceinline__ void cp_commit() {
    asm volatile("cp.async.commit_group;");
}
template<int N> __device__ __forceinline__ void cp_wait() {
    asm volatile("cp.async.wait_group %0;" :: "n"(N));
}
__device__ __forceinline__ void cp_wait_n(int n) {
    switch (n) {
        case 0:  cp_wait<0>(); break;
        case 1:  cp_wait<1>(); break;
        case 2:  cp_wait<2>(); break;
        default: cp_wait<3>(); break;
    }
}

// ---------------- prep: convert weights + transpose x (one launch) ---------
__global__ __launch_bounds__(256) void prep(
    const float* __restrict__ Wq, const float* __restrict__ Wk,
    const float* __restrict__ Wv, const float* __restrict__ Wp,
    const float* __restrict__ x)
{
    const int tid = threadIdx.x;
    if (blockIdx.x < 256) {
        // float4-vectorized weight convert: 4 matrices x 16384 float4 groups
        int idx = blockIdx.x * 256 + tid;          // 0..65535 float4 groups
        int y = idx >> 14, off4 = idx & 16383;
        const float* src = (y == 0) ? Wq : (y == 1) ? Wk : (y == 2) ? Wv : Wp;
        float4 v = ((const float4*)src)[off4];
        uint2 o;
        o.x = pack2(v.x, v.y);
        o.y = pack2(v.z, v.w);
        ((uint2*)(g_wh + (size_t)y * 65536))[off4] = o;
        return;
    }
    __shared__ float t[32][33];
    int tb = blockIdx.x - 256;
    int n0 = (tb & 31) * 32, c0 = ((tb >> 5) & 7) * 32, b = tb >> 8;
    int tx = tid & 31, ty = tid >> 5;  // 32 x 8
    const float* xb = x + ((size_t)b * C_DIM + c0) * HW + n0;
    #pragma unroll
    for (int r = 0; r < 32; r += 8) t[ty + r][tx] = xb[(ty + r) * HW + tx];
    __syncthreads();
    __half* xo = g_xh + ((size_t)b * HW + n0) * C_DIM + c0;
    #pragma unroll
    for (int r = 0; r < 32; r += 8)
        xo[(ty + r) * C_DIM + tx] = __float2half(t[tx][ty + r]);
}

// ---------------- QKV GEMM: D[n][m] = X[n,:]·W[m,:] ------------------------
// 128x128 tile, K chunks of 64, 3-stage cp.async pipeline.
__global__ __launch_bounds__(256, 2) void qkv_gemm(
    const float* __restrict__ bq, const float* __restrict__ bk,
    const float* __restrict__ bv)
{
    __shared__ __align__(16) __half smA[3][128 * 64];
    __shared__ __align__(16) __half smB[3][128 * 64];
    const int tid = threadIdx.x, lane = tid & 31, w = tid >> 5;
    const int wm = w >> 1, wn = w & 1;
    const int i0 = blockIdx.x * 128;     // HW rows
    const int n0 = blockIdx.y * 128;     // out channels
    const int p  = blockIdx.z % 3, b = blockIdx.z / 3;

    const __half* Ab = g_xh + ((size_t)b * HW + i0) * C_DIM;
    const __half* Bb = g_wh + (size_t)p * C_DIM * C_DIM + (size_t)n0 * C_DIM;
    uint32_t sA[3] = { cvta_s(smA[0]), cvta_s(smA[1]), cvta_s(smA[2]) };
    uint32_t sB[3] = { cvta_s(smB[0]), cvta_s(smB[1]), cvta_s(smB[2]) };

    float acc[2][8][4] = {};

    // prefetch chunks 0 and 1 (one group each)
    #pragma unroll
    for (int pc = 0; pc < 2; pc++) {
        int k0 = pc * 64;
        #pragma unroll
        for (int s = tid; s < 1024; s += 256) {
            int row = s >> 3, c = s & 7;
            uint32_t so = row * 128 + ((c ^ (row & 7)) << 4);
            cp16(sA[pc] + so, Ab + row * C_DIM + k0 + c * 8);
            cp16(sB[pc] + so, Bb + row * C_DIM + k0 + c * 8);
        }
        cp_commit();
    }

    for (int kc = 0; kc < 4; kc++) {
        if (kc) __syncthreads();          // stage (kc+2)%3 free (compute kc-1 done)
        if (kc + 2 < 4) {
            int st = (kc + 2) % 3, k0 = (kc + 2) * 64;
            #pragma unroll
            for (int s = tid; s < 1024; s += 256) {
                int row = s >> 3, c = s & 7;
                uint32_t so = row * 128 + ((c ^ (row & 7)) << 4);
                cp16(sA[st] + so, Ab + row * C_DIM + k0 + c * 8);
                cp16(sB[st] + so, Bb + row * C_DIM + k0 + c * 8);
            }
        }
        cp_commit();
        cp_wait_n(3 - kc >= 2 ? 2 : 3 - kc);
        __syncthreads();
        const uint32_t cA = sA[kc % 3], cB = sB[kc % 3];
        #pragma unroll
        for (int ki = 0; ki < 4; ki++) {
            uint32_t a[2][4];
            #pragma unroll
            for (int mi = 0; mi < 2; mi++) {
                int r = wm * 32 + mi * 16 + (lane & 15);
                int c = ki * 2 + (lane >> 4);
                ldsm4(a[mi][0], a[mi][1], a[mi][2], a[mi][3],
                      cA + r * 128 + ((c ^ (r & 7)) << 4));
            }
            #pragma unroll
            for (int nj = 0; nj < 4; nj++) {
                int r = wn * 64 + nj * 16 + ((lane >> 4) << 3) + (lane & 7);
                int c = ki * 2 + ((lane >> 3) & 1);
                uint32_t bb[4];
                ldsm4(bb[0], bb[1], bb[2], bb[3],
                      cB + r * 128 + ((c ^ (r & 7)) << 4));
                #pragma unroll
                for (int mi = 0; mi < 2; mi++) {
                    mma16816(acc[mi][2 * nj],     a[mi], bb);
                    mma16816(acc[mi][2 * nj + 1], a[mi], bb + 2);
                }
            }
        }
    }

    const float* bias = (p == 0) ? bq : (p == 1) ? bk : bv;
    __half* dst = ((p == 0) ? g_q : (p == 1) ? g_k : g_v) + (size_t)b * HW * C_DIM;
    // Q scale = (1/sqrt(32)) * log2(e)  — softmax runs in the log2 domain
    const float scl = (p == 0) ? 0.25503485f : 1.0f;
    #pragma unroll
    for (int mi = 0; mi < 2; mi++) {
        int r0 = i0 + wm * 32 + mi * 16 + (lane >> 2);
        #pragma unroll
        for (int nf = 0; nf < 8; nf++) {
            int m = n0 + wn * 64 + nf * 8 + 2 * (lane & 3);
            float b0 = bias[m], b1 = bias[m + 1];
            *(uint32_t*)(dst + (size_t)r0 * C_DIM + m) =
                pack2((acc[mi][nf][0] + b0) * scl, (acc[mi][nf][1] + b1) * scl);
            *(uint32_t*)(dst + (size_t)(r0 + 8) * C_DIM + m) =
                pack2((acc[mi][nf][2] + b0) * scl, (acc[mi][nf][3] + b1) * scl);
        }
    }
}

// ---------------- attention: CTA per (64-row q-tile, h, b) -----------------
// 4 warps as 2(row)x2(j): warp = 32 q-rows x 64 j. Row sums computed from P
// fragments on the fma pipe (no ones-column MMA). Partial O reduced via smem.
// Fragment rows: pa[0],pa[2] belong to row r; pa[1],pa[3] to row r+8.
__global__ __launch_bounds__(128) void attn_kernel()
{
    __shared__ __align__(16) __half q_s[64 * 32];
    __shared__ __align__(16) __half k_s[2][128 * 32];
    __shared__ __align__(16) __half v_s[2][128 * 32];
    const int tid = threadIdx.x, lane = tid & 31, w = tid >> 5;
    const int wr = w & 1, wc = w >> 1;
    const int qi = blockIdx.x, h = blockIdx.y, b = blockIdx.z;

    const __half* Qb = g_q + ((size_t)b * HW + qi * 64) * C_DIM + h * HD;
    const __half* Kb = g_k + (size_t)b * HW * C_DIM + h * HD;
    const __half* Vb = g_v + (size_t)b * HW * C_DIM + h * HD;
    uint32_t sQ = cvta_s(q_s);
    uint32_t sK[2] = { cvta_s(k_s[0]), cvta_s(k_s[1]) };
    uint32_t sV[2] = { cvta_s(v_s[0]), cvta_s(v_s[1]) };

    // Q tile load (64 rows)
    #pragma unroll
    for (int s2 = tid; s2 < 256; s2 += 128) {
        int row = s2 >> 2, c = s2 & 3;
        *(uint4*)((char*)q_s + row * 64 + ((c ^ ((row >> 1) & 3)) << 4)) =
            *(const uint4*)(Qb + row * C_DIM + c * 8);
    }
    // prefetch K/V tile 0
    #pragma unroll
    for (int s2 = tid; s2 < 512; s2 += 128) {
        int row = s2 >> 2, c = s2 & 3;
        uint32_t so = row * 64 + ((c ^ ((row >> 1) & 3)) << 4);
        cp16(sK[0] + so, Kb + (size_t)row * C_DIM + c * 8);
        cp16(sV[0] + so, Vb + (size_t)row * C_DIM + c * 8);
    }
    cp_commit();
    __syncthreads();

    // Q fragments: rows wr*32 + rb*16
    uint32_t qa[2][2][4];
    #pragma unroll
    for (int rb = 0; rb < 2; rb++)
        #pragma unroll
        for (int ki = 0; ki < 2; ki++) {
            int r = wr * 32 + rb * 16 + (lane & 15);
            int c = ki * 2 + (lane >> 4);
            ldsm4(qa[rb][ki][0], qa[rb][ki][1], qa[rb][ki][2], qa[rb][ki][3],
                  sQ + r * 64 + ((c ^ ((r >> 1) & 3)) << 4));
        }

    float o[2][4][4] = {};
    float ps0[2] = {0.f, 0.f};   // row-sum partials: rows r   (pa[0], pa[2])
    float ps1[2] = {0.f, 0.f};   // rows r+8                   (pa[1], pa[3])

    for (int kt = 0; kt < 8; kt++) {
        if (kt) __syncthreads();   // prev compute done before overwriting buf
        if (kt + 1 < 8) {
            int nb = (kt + 1) & 1;
            #pragma unroll
            for (int s2 = tid; s2 < 512; s2 += 128) {
                int row = s2 >> 2, c = s2 & 3;
                uint32_t so = row * 64 + ((c ^ ((row >> 1) & 3)) << 4);
                cp16(sK[nb] + so, Kb + (size_t)((kt + 1) * 128 + row) * C_DIM + c * 8);
                cp16(sV[nb] + so, Vb + (size_t)((kt + 1) * 128 + row) * C_DIM + c * 8);
            }
        }
        cp_commit();
        cp_wait<1>();
        __syncthreads();
        const uint32_t cK = sK[kt & 1], cV = sV[kt & 1];

        // per 16-j chunk of this warp's j-half: S -> exp -> PV
        #pragma unroll
        for (int kf = 0; kf < 4; kf++) {
            int j0 = wc * 64 + kf * 16;
            // K fragments as B operands
            uint32_t bb[2][4];
            #pragma unroll
            for (int ki = 0; ki < 2; ki++) {
                int r = j0 + ((lane >> 4) << 3) + (lane & 7);
                int c = ki * 2 + ((lane >> 3) & 1);
                ldsm4(bb[ki][0], bb[ki][1], bb[ki][2], bb[ki][3],
                      cK + r * 64 + ((c ^ ((r >> 1) & 3)) << 4));
            }
            // S + exp -> P fragments per row-block; row sums on fma pipe
            uint32_t pa[2][4];
            #pragma unroll
            for (int rb = 0; rb < 2; rb++) {
                float sc0[4] = {0.f, 0.f, 0.f, 0.f};
                float sc1[4] = {0.f, 0.f, 0.f, 0.f};
                #pragma unroll
                for (int ki = 0; ki < 2; ki++) {
                    mma16816(sc0, qa[rb][ki], bb[ki]);
                    mma16816(sc1, qa[rb][ki], bb[ki] + 2);
                }
                pa[rb][0] = ex2_h2(pack2(sc0[0], sc0[1]));   // row r,   j 0-1
                pa[rb][1] = ex2_h2(pack2(sc0[2], sc0[3]));   // row r+8, j 0-1
                pa[rb][2] = ex2_h2(pack2(sc1[0], sc1[1]));   // row r,   j 8-9
                pa[rb][3] = ex2_h2(pack2(sc1[2], sc1[3]));   // row r+8, j 8-9
                __half2 h0 = __hadd2(*(__half2*)&pa[rb][0], *(__half2*)&pa[rb][2]);
                __half2 h1 = __hadd2(*(__half2*)&pa[rb][1], *(__half2*)&pa[rb][3]);
                float2 f0 = __half22float2(h0);
                float2 f1 = __half22float2(h1);
                ps0[rb] += f0.x + f0.y;
                ps1[rb] += f1.x + f1.y;
            }
            // V fragments + PV
            #pragma unroll
            for (int ndp = 0; ndp < 2; ndp++) {
                uint32_t vb[4];
                int r = j0 + (lane & 15);
                int ch = ndp * 2 + (lane >> 4);
                ldsm4t(vb[0], vb[1], vb[2], vb[3],
                       cV + r * 64 + ((ch ^ ((r >> 1) & 3)) << 4));
                #pragma unroll
                for (int rb = 0; rb < 2; rb++) {
                    mma16816(o[rb][ndp * 2],     pa[rb], vb);
                    mma16816(o[rb][ndp * 2 + 1], pa[rb], vb + 2);
                }
            }
        }
    }

    // reduce row-sum partials across the 4 lanes sharing each row
    #pragma unroll
    for (int rb = 0; rb < 2; rb++) {
        ps0[rb] += __shfl_xor_sync(0xffffffffu, ps0[rb], 1);
        ps0[rb] += __shfl_xor_sync(0xffffffffu, ps0[rb], 2);
        ps1[rb] += __shfl_xor_sync(0xffffffffu, ps1[rb], 1);
        ps1[rb] += __shfl_xor_sync(0xffffffffu, ps1[rb], 2);
    }

    // ---- cross-warp (j-halves) O reduction via smem, then store ----
    __syncthreads();
    float* stageO = (float*)k_s;            // 64 rows x stride 36 floats
    float* stageS = (float*)v_s;            // 64 floats
    if (wc == 1) {
        #pragma unroll
        for (int rb = 0; rb < 2; rb++) {
            int r = wr * 32 + rb * 16 + (lane >> 2);
            #pragma unroll
            for (int nd = 0; nd < 4; nd++) {
                int cc = nd * 8 + 2 * (lane & 3);
                stageO[r * 36 + cc]           = o[rb][nd][0];
                stageO[r * 36 + cc + 1]       = o[rb][nd][1];
                stageO[(r + 8) * 36 + cc]     = o[rb][nd][2];
                stageO[(r + 8) * 36 + cc + 1] = o[rb][nd][3];
            }
            if ((lane & 3) == 0) {
                stageS[r]     = ps0[rb];
                stageS[r + 8] = ps1[rb];
            }
        }
    }
    __syncthreads();
    if (wc == 0) {
        #pragma unroll
        for (int rb = 0; rb < 2; rb++) {
            int r = wr * 32 + rb * 16 + (lane >> 2);
            float rs0 = ps0[rb] + stageS[r];
            float rs1 = ps1[rb] + stageS[r + 8];
            float inv0 = 1.f / rs0, inv1 = 1.f / rs1;
            __half* dst = g_at + ((size_t)b * HW + qi * 64 + r) * C_DIM + h * HD;
            #pragma unroll
            for (int nd = 0; nd < 4; nd++) {
                int cc = nd * 8 + 2 * (lane & 3);
                float v0 = o[rb][nd][0] + stageO[r * 36 + cc];
                float v1 = o[rb][nd][1] + stageO[r * 36 + cc + 1];
                float v2 = o[rb][nd][2] + stageO[(r + 8) * 36 + cc];
                float v3 = o[rb][nd][3] + stageO[(r + 8) * 36 + cc + 1];
                *(uint32_t*)(dst + cc) = pack2(v0 * inv0, v1 * inv0);
                *(uint32_t*)(dst + 8 * C_DIM + cc) = pack2(v2 * inv1, v3 * inv1);
            }
        }
    }
}

// ---------------- proj + bias + residual + LayerNorm (fused) ---------------
// Persistent: grid 128 CTAs, each handles TWO 32-row tiles. Full Wp (128KB)
// + both A tiles (32KB) live in dynamic smem; ALL loads issued upfront as 4
// commit groups, so the mainloop is wait/sync/compute with no reuse hazards.
#define PLN_BOFF   0                       // B: 4 chunks x 32KB
#define PLN_AOFF   131072                  // A: 2 tiles x 16KB (4KB per chunk)
#define PLN_SMEM   (131072 + 32768)
__global__ __launch_bounds__(256) void proj_ln(
    const float* __restrict__ bp, const float* __restrict__ gamma,
    const float* __restrict__ beta, const float* __restrict__ x,
    float* __restrict__ out)
{
    extern __shared__ __align__(16) char dsm[];
    __shared__ float redS[2][32][4];
    __shared__ float redQ[2][32][4];
    const int tid = threadIdx.x, lane = tid & 31, w = tid >> 5;
    const int wm = w >> 2, wn = w & 3;
    uint32_t sm = cvta_s(dsm);

    // tile ids: T(t) = blockIdx.x + t*128 ; b = T>>5 ; i0 = (T&31)*32
    int Tb[2], Ti[2];
    #pragma unroll
    for (int t = 0; t < 2; t++) {
        int T = blockIdx.x + t * 128;
        Tb[t] = T >> 5;
        Ti[t] = (T & 31) * 32;
    }
    const __half* Bb = g_wh + (size_t)3 * C_DIM * C_DIM;

    // ---- issue ALL loads: group0 = A(t0)+A(t1)+B0 ; groups 1..3 = B1..B3 ----
    #pragma unroll
    for (int t = 0; t < 2; t++) {
        const __half* Ab = g_at + ((size_t)Tb[t] * HW + Ti[t]) * C_DIM;
        #pragma unroll
        for (int s = tid; s < 1024; s += 256) {     // 32 rows x 8 col-groups x 4 chunks
            int c4 = s >> 8, row = (s >> 3) & 31, cc = s & 7;
            cp16(sm + PLN_AOFF + t * 16384 + c4 * 4096
                     + row * 128 + ((cc ^ (row & 7)) << 4),
                 Ab + row * C_DIM + c4 * 64 + cc * 8);
        }
    }
    #pragma unroll
    for (int s = tid; s < 2048; s += 256) {         // B chunk 0
        int row = s >> 3, cc = s & 7;
        cp16(sm + row * 128 + ((cc ^ (row & 7)) << 4), Bb + row * C_DIM + cc * 8);
    }
    cp_commit();
    #pragma unroll
    for (int c4 = 1; c4 < 4; c4++) {
        #pragma unroll
        for (int s = tid; s < 2048; s += 256) {
            int row = s >> 3, cc = s & 7;
            cp16(sm + c4 * 32768 + row * 128 + ((cc ^ (row & 7)) << 4),
                 Bb + row * C_DIM + c4 * 64 + cc * 8);
        }
        cp_commit();
    }

    float acc[2][8][4] = {};

    for (int c4 = 0; c4 < 4; c4++) {
        cp_wait_n(3 - c4);
        __syncthreads();
        const uint32_t cB = sm + c4 * 32768;
        #pragma unroll
        for (int ki = 0; ki < 4; ki++) {
            uint32_t a[2][4];
            #pragma unroll
            for (int t = 0; t < 2; t++) {
                int r = wm * 16 + (lane & 15);
                int c = ki * 2 + (lane >> 4);
                ldsm4(a[t][0], a[t][1], a[t][2], a[t][3],
                      sm + PLN_AOFF + t * 16384 + c4 * 4096
                         + r * 128 + ((c ^ (r & 7)) << 4));
            }
            #pragma unroll
            for (int nj = 0; nj < 4; nj++) {
                int r = wn * 64 + nj * 16 + ((lane >> 4) << 3) + (lane & 7);
                int c = ki * 2 + ((lane >> 3) & 1);
                uint32_t bb[4];
                ldsm4(bb[0], bb[1], bb[2], bb[3],
                      cB + r * 128 + ((c ^ (r & 7)) << 4));
                #pragma unroll
                for (int t = 0; t < 2; t++) {
                    mma16816(acc[t][2 * nj],     a[t], bb);
                    mma16816(acc[t][2 * nj + 1], a[t], bb + 2);
                }
            }
        }
    }

    // ---- epilogues (both tiles): bias + residual, LN stats, store ----
    const int r0 = wm * 16 + (lane >> 2);
    #pragma unroll
    for (int t = 0; t < 2; t++) {
        float s0 = 0.f, q0 = 0.f, s1 = 0.f, q1 = 0.f;
        #pragma unroll
        for (int nf = 0; nf < 8; nf++) {
            int m = wn * 64 + nf * 8 + 2 * (lane & 3);
            const float* xp = x + ((size_t)Tb[t] * C_DIM + m) * HW + Ti[t];
            float b0 = bp[m], b1 = bp[m + 1];
            acc[t][nf][0] += b0 + xp[r0];
            acc[t][nf][1] += b1 + xp[HW + r0];
            acc[t][nf][2] += b0 + xp[r0 + 8];
            acc[t][nf][3] += b1 + xp[HW + r0 + 8];
            s0 += acc[t][nf][0] + acc[t][nf][1];
            q0 += acc[t][nf][0] * acc[t][nf][0] + acc[t][nf][1] * acc[t][nf][1];
            s1 += acc[t][nf][2] + acc[t][nf][3];
            q1 += acc[t][nf][2] * acc[t][nf][2] + acc[t][nf][3] * acc[t][nf][3];
        }
        s0 += __shfl_xor_sync(0xffffffffu, s0, 1); s0 += __shfl_xor_sync(0xffffffffu, s0, 2);
        q0 += __shfl_xor_sync(0xffffffffu, q0, 1); q0 += __shfl_xor_sync(0xffffffffu, q0, 2);
        s1 += __shfl_xor_sync(0xffffffffu, s1, 1); s1 += __shfl_xor_sync(0xffffffffu, s1, 2);
        q1 += __shfl_xor_sync(0xffffffffu, q1, 1); q1 += __shfl_xor_sync(0xffffffffu, q1, 2);
        if ((lane & 3) == 0) {
            redS[t][r0][wn] = s0; redQ[t][r0][wn] = q0;
            redS[t][r0 + 8][wn] = s1; redQ[t][r0 + 8][wn] = q1;
        }
    }
    __syncthreads();
    #pragma unroll
    for (int t = 0; t < 2; t++) {
        float mu0 = (redS[t][r0][0] + redS[t][r0][1] + redS[t][r0][2] + redS[t][r0][3])
                    * (1.f / 256.f);
        float v0  = (redQ[t][r0][0] + redQ[t][r0][1] + redQ[t][r0][2] + redQ[t][r0][3])
                    * (1.f / 256.f) - mu0 * mu0;
        float rg0 = rsqrtf(v0 + 1e-5f);
        float mu1 = (redS[t][r0 + 8][0] + redS[t][r0 + 8][1] + redS[t][r0 + 8][2]
                     + redS[t][r0 + 8][3]) * (1.f / 256.f);
        float v1  = (redQ[t][r0 + 8][0] + redQ[t][r0 + 8][1] + redQ[t][r0 + 8][2]
                     + redQ[t][r0 + 8][3]) * (1.f / 256.f) - mu1 * mu1;
        float rg1 = rsqrtf(v1 + 1e-5f);
        #pragma unroll
        for (int nf = 0; nf < 8; nf++) {
            int m = wn * 64 + nf * 8 + 2 * (lane & 3);
            float g0 = gamma[m], g1 = gamma[m + 1];
            float e0 = beta[m],  e1 = beta[m + 1];
            float* op = out + ((size_t)Tb[t] * C_DIM + m) * HW + Ti[t];
            op[r0]          = (acc[t][nf][0] - mu0) * rg0 * g0 + e0;
            op[HW + r0]     = (acc[t][nf][1] - mu0) * rg0 * g1 + e1;
            op[r0 + 8]      = (acc[t][nf][2] - mu1) * rg1 * g0 + e0;
            op[HW + r0 + 8] = (acc[t][nf][3] - mu1) * rg1 * g1 + e1;
        }
    }
}

// ---------------------------------------------------------------------------
extern "C" void kernel_launch(void* const* d_in, const int* in_sizes, int n_in,
                              void* d_out, int out_size)
{
    const float* x     = (const float*)d_in[0];
    const float* Wq    = (const float*)d_in[1];
    const float* bq    = (const float*)d_in[2];
    const float* Wk    = (const float*)d_in[3];
    const float* bk    = (const float*)d_in[4];
    const float* Wv    = (const float*)d_in[5];
    const float* bv    = (const float*)d_in[6];
    const float* Wp    = (const float*)d_in[7];
    const float* bp    = (const float*)d_in[8];
    const float* gamma = (const float*)d_in[9];
    const float* beta  = (const float*)d_in[10];
    float* out = (float*)d_out;

    cudaFuncSetAttribute(proj_ln, cudaFuncAttributeMaxDynamicSharedMemorySize,
                         PLN_SMEM);

    prep<<<2304, 256>>>(Wq, Wk, Wv, Wp, x);
    qkv_gemm<<<dim3(HW / 128, C_DIM / 128, B_DIM * 3), 256>>>(bq, bk, bv);
    attn_kernel<<<dim3(HW / 64, NH, B_DIM), 128>>>();
    proj_ln<<<128, 256, PLN_SMEM>>>(bp, gamma, beta, x, out);
}